// round 17
// baseline (speedup 1.0000x reference)
#include <cuda_runtime.h>
#include <cuda_fp16.h>
#include <cstdint>

// ============================================================================
// Problem constants
// ============================================================================
#define NQ     6
#define DIM    64
#define NL     8
#define GRIDB  296           // persistent CTAs (148 SMs x 2)
#define NPAIRS (GRIDB * 4)   // 4 warp-pairs per CTA

// Circuit constants built per-launch by qnn_build.
__device__ __align__(16) __half g_Wh[128 * 64];
__device__ __align__(16) float4 g_Mt[64];   // Mt[a] = {M[0][a],..,M[3][a]}, M = fc_w * Zsign^T
__device__ __align__(16) float4 g_fcb;
__device__ int g_ctr;                       // dynamic work counter (reset each launch)

// ============================================================================
// PTX helpers (plain sm_103-legal)
// ============================================================================
__device__ __forceinline__ uint32_t smem_u32(const void* p) {
    uint32_t a;
    asm("{ .reg .u64 t; cvta.to.shared.u64 t, %1; cvt.u32.u64 %0, t; }" : "=r"(a) : "l"(p));
    return a;
}
__device__ __forceinline__ void ldsm_x4(uint32_t* r, uint32_t addr) {
    asm volatile("ldmatrix.sync.aligned.m8n8.x4.shared.b16 {%0,%1,%2,%3}, [%4];"
                 : "=r"(r[0]), "=r"(r[1]), "=r"(r[2]), "=r"(r[3]) : "r"(addr));
}
__device__ __forceinline__ void mma16816(float* c, const uint32_t* a, const uint32_t* b) {
    asm volatile("mma.sync.aligned.m16n8k16.row.col.f32.f16.f16.f32 "
                 "{%0,%1,%2,%3}, {%4,%5,%6,%7}, {%8,%9}, {%0,%1,%2,%3};"
                 : "+f"(c[0]), "+f"(c[1]), "+f"(c[2]), "+f"(c[3])
                 : "r"(a[0]), "r"(a[1]), "r"(a[2]), "r"(a[3]), "r"(b[0]), "r"(b[1]));
}
__device__ __forceinline__ void barx(int id) {
    asm volatile("bar.sync %0, %1;" :: "r"(id), "r"(64) : "memory");
}

// ============================================================================
// Kernel A: build U columns (one warp per basis column), emit Wh/Mt/fcb,
// reset the dynamic-work counter.
// ============================================================================
__global__ void qnn_build(const float* __restrict__ weights,
                          const float* __restrict__ fc_w,
                          const float* __restrict__ fc_b) {
    const int w = blockIdx.x;
    const int lane = threadIdx.x;

    if (w == 0 && lane == 0) g_ctr = NPAIRS;   // first units taken statically

    float sr0 = (lane == w) ? 1.f : 0.f,      si0 = 0.f;
    float sr1 = (lane + 32 == w) ? 1.f : 0.f, si1 = 0.f;

    for (int l = 0; l < NL; l++) {
        for (int q = 0; q < NQ; q++) {
            const float* g = weights + (l * NQ + q) * 3;
            float phi = g[0], th = g[1], om = g[2];
            float st, ct; sincosf(0.5f * th, &st, &ct);
            float sa, ca; sincosf(0.5f * (phi + om), &sa, &ca);
            float sb, cb; sincosf(0.5f * (phi - om), &sb, &cb);
            float m00r =  ca * ct, m00i = -sa * ct;
            float m01r = -cb * st, m01i = -sb * st;
            float m10r =  cb * st, m10i = -sb * st;
            float m11r =  ca * ct, m11i =  sa * ct;
            int b = 5 - q;
            if (b == 5) {
                float nr0 = m00r*sr0 - m00i*si0 + m01r*sr1 - m01i*si1;
                float ni0 = m00r*si0 + m00i*sr0 + m01r*si1 + m01i*sr1;
                float nr1 = m10r*sr0 - m10i*si0 + m11r*sr1 - m11i*si1;
                float ni1 = m10r*si0 + m10i*sr0 + m11r*si1 + m11i*sr1;
                sr0 = nr0; si0 = ni0; sr1 = nr1; si1 = ni1;
            } else {
                int msk = 1 << b;
                int bit = (lane >> b) & 1;
                float dr = bit ? m11r : m00r, di = bit ? m11i : m00i;
                float orr = bit ? m10r : m01r, oi = bit ? m10i : m01i;
                float pr, pi, nr, ni;
                pr = __shfl_xor_sync(0xffffffffu, sr0, msk);
                pi = __shfl_xor_sync(0xffffffffu, si0, msk);
                nr = dr*sr0 - di*si0 + orr*pr - oi*pi;
                ni = dr*si0 + di*sr0 + orr*pi + oi*pr;
                sr0 = nr; si0 = ni;
                pr = __shfl_xor_sync(0xffffffffu, sr1, msk);
                pi = __shfl_xor_sync(0xffffffffu, si1, msk);
                nr = dr*sr1 - di*si1 + orr*pr - oi*pi;
                ni = dr*si1 + di*sr1 + orr*pi + oi*pr;
                sr1 = nr; si1 = ni;
            }
        }
        int r = (l % (NQ - 1)) + 1;
        for (int q = 0; q < NQ; q++) {
            int t = (q + r) % NQ;
            int bc = 5 - q, bt = 5 - t;
            if (bc == 5) {
                int m = 1 << bt;
                sr1 = __shfl_xor_sync(0xffffffffu, sr1, m);
                si1 = __shfl_xor_sync(0xffffffffu, si1, m);
            } else if (bt == 5) {
                if ((lane >> bc) & 1) {
                    float tmp;
                    tmp = sr0; sr0 = sr1; sr1 = tmp;
                    tmp = si0; si0 = si1; si1 = tmp;
                }
            } else {
                int m = 1 << bt;
                int ctrl = (lane >> bc) & 1;
                float pr, pi;
                pr = __shfl_xor_sync(0xffffffffu, sr0, m);
                pi = __shfl_xor_sync(0xffffffffu, si0, m);
                if (ctrl) { sr0 = pr; si0 = pi; }
                pr = __shfl_xor_sync(0xffffffffu, sr1, m);
                pi = __shfl_xor_sync(0xffffffffu, si1, m);
                if (ctrl) { sr1 = pr; si1 = pi; }
            }
        }
    }

    g_Wh[(2 * lane)            * 64 + w] = __float2half(sr0);
    g_Wh[(2 * lane + 1)        * 64 + w] = __float2half(si0);
    g_Wh[(2 * (lane + 32))     * 64 + w] = __float2half(sr1);
    g_Wh[(2 * (lane + 32) + 1) * 64 + w] = __float2half(si1);

    if (w == 0) {
        for (int s = 0; s < 2; s++) {
            int d = lane + 32 * s;
            float m[4];
            for (int c = 0; c < 4; c++) {
                float acc = 0.f;
                for (int i = 0; i < NQ; i++) {
                    int bit = (d >> (5 - i)) & 1;
                    acc += fc_w[c * NQ + i] * (bit ? -1.f : 1.f);
                }
                m[c] = acc;
            }
            g_Mt[d] = make_float4(m[0], m[1], m[2], m[3]);
        }
        if (lane == 0)
            g_fcb = make_float4(fc_b[0], fc_b[1], fc_b[2], fc_b[3]);
    }
}

// ============================================================================
// Kernel B: persistent, 256 thr = 4 warp-pairs.  Pair = (warp nh=0, warp nh=1)
// covering N halves [0,64) and [64,128).  Each warp keeps its entire B slice
// in 64 REGISTERS (loaded once via 16 ldsm at init) -> ZERO ldsm in the work
// loop.  Work unit (per pair, dynamic): 16 rows; A fragments come straight
// from LDG.128 via the k-permutation (slots {2q,2q+1,2q+8,2q+9} <-> cols
// {4q..4q+3}).  Per-unit sync: ONE 64-thread named barrier for the class-dot
// exchange (parity double-buffered) + u_next publication.
// ============================================================================
#define STRIDE_B 144                          // 128B data + 16B pad
#define OF_MT   0                             // 64 float4 = 1 KB
#define OF_XB   1024                          // 4 pairs x 2 parity x 16 x 16B = 2 KB
#define OF_UB   3072                          // 4 pairs x 2 parity x int (pad 128B)
#define OF_B    3200                          // B staging (only used at init)
#define SMEM_BYTES (OF_B + 128 * STRIDE_B)    // 3200 + 18432 = 21632

__global__ void __launch_bounds__(256, 2)
qnn_main(const float4* __restrict__ X, float4* __restrict__ out, int ntiles16) {
    extern __shared__ char smc[];
    const uint32_t sm = smem_u32(smc);
    const int tid = threadIdx.x, wid = tid >> 5, lane = tid & 31;

    // ---- one-time staging: B[wrow][kpos] = Wh[wrow][colmap(kpos)] ----
    for (int idx = tid; idx < 128 * 64; idx += 256) {
        int wrow = idx >> 6, kpos = idx & 63;
        int col = (kpos & ~15) + 4 * ((kpos & 7) >> 1) + 2 * ((kpos >> 3) & 1) + (kpos & 1);
        __half v = g_Wh[wrow * 64 + col];
        *reinterpret_cast<__half*>(smc + OF_B + wrow * STRIDE_B + kpos * 2) = v;
    }
    if (tid < 64) reinterpret_cast<float4*>(smc + OF_MT)[tid] = g_Mt[tid];
    const float4 fcb = g_fcb;
    __syncthreads();

    const int pair = wid & 3;             // 0..3
    const int nh   = wid >> 2;            // N half: 0 -> cols 0-63, 1 -> cols 64-127
    const int l4   = lane & 3;
    const int lq   = lane >> 2;           // 0..7

    // ---- load this warp's B slice into 64 registers (16 ldsm, once) ----
    const uint32_t bB = sm + OF_B
        + (uint32_t)(nh * 64 + ((lane >> 4) & 1) * 8 + (lane & 7)) * STRIDE_B
        + ((lane >> 3) & 1) * 16;
    uint32_t breg[4][4][4];               // [pr][kc][frag]
    #pragma unroll
    for (int pr = 0; pr < 4; pr++)
        #pragma unroll
        for (int kc = 0; kc < 4; kc++)
            ldsm_x4(breg[pr][kc], bB + (uint32_t)(pr * 16) * STRIDE_B + kc * 32);

    const float4* sMt = reinterpret_cast<const float4*>(smc + OF_MT);
    float4* xbuf = reinterpret_cast<float4*>(smc + OF_XB) + pair * 32;   // [par*16 + row] per pair? layout below
    int*    ubuf = reinterpret_cast<int*>(smc + OF_UB) + pair * 2;       // [par]

    const int nunit = ntiles16;           // 16384 units of 16 rows
    int u = blockIdx.x * 4 + pair;        // static first wave (NPAIRS units)
    int par = 0;

    while (u < nunit) {
        // ---- role-0 fetches next unit and publishes it pre-barrier ----
        int u_next = 0;
        if (nh == 0) {
            if (lane == 0) {
                u_next = atomicAdd(&g_ctr, 1);
                ubuf[par] = u_next;
            }
            u_next = __shfl_sync(0xffffffffu, u_next, 0);
        }

        const int row0 = u * 16 + lq;     // this thread's rows: row0, row0+8

        // ---- A fragments: 8 LDG.128 -> fp16 frags; row sumsq ----
        uint32_t ah[4][4];
        float ss0 = 0.f, ss1 = 0.f;
        #pragma unroll
        for (int kc = 0; kc < 4; kc++) {
            const size_t rb = (size_t)row0 * 16 + l4 + 4 * kc;
            float4 v0 = X[rb];
            float4 v1 = X[rb + 128];      // +8 rows * 16
            ss0 += v0.x * v0.x + v0.y * v0.y + v0.z * v0.z + v0.w * v0.w;
            ss1 += v1.x * v1.x + v1.y * v1.y + v1.z * v1.z + v1.w * v1.w;
            __half2 h00 = __floats2half2_rn(v0.x, v0.y);
            __half2 h01 = __floats2half2_rn(v0.z, v0.w);
            __half2 h10 = __floats2half2_rn(v1.x, v1.y);
            __half2 h11 = __floats2half2_rn(v1.z, v1.w);
            ah[kc][0] = *reinterpret_cast<uint32_t*>(&h00);
            ah[kc][1] = *reinterpret_cast<uint32_t*>(&h10);
            ah[kc][2] = *reinterpret_cast<uint32_t*>(&h01);
            ah[kc][3] = *reinterpret_cast<uint32_t*>(&h11);
        }

        // ---- 32 HMMAs, all operands in registers ----
        float c[8][4];
        #pragma unroll
        for (int j = 0; j < 8; j++)
            #pragma unroll
            for (int q = 0; q < 4; q++) c[j][q] = 0.f;
        #pragma unroll
        for (int kc = 0; kc < 4; kc++)
            #pragma unroll
            for (int pr = 0; pr < 4; pr++) {
                mma16816(c[pr * 2],     ah[kc], breg[pr][kc]);
                mma16816(c[pr * 2 + 1], ah[kc], breg[pr][kc] + 2);
            }

        // ---- epilogue: p = re^2 + im^2 ; 4-class dot against Mt ----
        float a0[4] = {0.f, 0.f, 0.f, 0.f}, a1[4] = {0.f, 0.f, 0.f, 0.f};
        #pragma unroll
        for (int j = 0; j < 8; j++) {
            const int amp = nh * 32 + j * 4 + l4;
            float4 mt = sMt[amp];
            float p0 = c[j][0] * c[j][0] + c[j][1] * c[j][1];
            float p1 = c[j][2] * c[j][2] + c[j][3] * c[j][3];
            a0[0] += mt.x * p0; a0[1] += mt.y * p0; a0[2] += mt.z * p0; a0[3] += mt.w * p0;
            a1[0] += mt.x * p1; a1[1] += mt.y * p1; a1[2] += mt.z * p1; a1[3] += mt.w * p1;
        }
        // quad reductions
        ss0 += __shfl_xor_sync(0xffffffffu, ss0, 1);
        ss0 += __shfl_xor_sync(0xffffffffu, ss0, 2);
        ss1 += __shfl_xor_sync(0xffffffffu, ss1, 1);
        ss1 += __shfl_xor_sync(0xffffffffu, ss1, 2);
        #pragma unroll
        for (int q = 0; q < 4; q++) {
            a0[q] += __shfl_xor_sync(0xffffffffu, a0[q], 1);
            a0[q] += __shfl_xor_sync(0xffffffffu, a0[q], 2);
            a1[q] += __shfl_xor_sync(0xffffffffu, a1[q], 1);
            a1[q] += __shfl_xor_sync(0xffffffffu, a1[q], 2);
        }

        // ---- pair exchange via smem (parity-buffered), one named barrier ----
        float4* xbp = xbuf + par * 16;
        if (nh == 1) {
            if (l4 == 0) {
                xbp[lq]     = make_float4(a0[0], a0[1], a0[2], a0[3]);
                xbp[lq + 8] = make_float4(a1[0], a1[1], a1[2], a1[3]);
            }
        }
        barx(1 + pair);
        if (nh == 0) {
            if (l4 == 0) {
                float4 o0 = xbp[lq];
                float4 o1 = xbp[lq + 8];
                float inv0 = 1.f / fmaxf(ss0, 1e-24f);
                float inv1 = 1.f / fmaxf(ss1, 1e-24f);
                float4 r;
                r.x = (a0[0] + o0.x) * inv0 + fcb.x;
                r.y = (a0[1] + o0.y) * inv0 + fcb.y;
                r.z = (a0[2] + o0.z) * inv0 + fcb.z;
                r.w = (a0[3] + o0.w) * inv0 + fcb.w;
                out[row0] = r;
                r.x = (a1[0] + o1.x) * inv1 + fcb.x;
                r.y = (a1[1] + o1.y) * inv1 + fcb.y;
                r.z = (a1[2] + o1.z) * inv1 + fcb.z;
                r.w = (a1[3] + o1.w) * inv1 + fcb.w;
                out[row0 + 8] = r;
            }
            u = u_next;
        } else {
            u = ubuf[par];                 // broadcast LDS
        }
        par ^= 1;
    }
}

// ============================================================================
// Launch
// ============================================================================
extern "C" void kernel_launch(void* const* d_in, const int* in_sizes, int n_in,
                              void* d_out, int out_size) {
    const float* x    = (const float*)d_in[0];
    const float* wts  = (const float*)d_in[1];
    const float* fc_w = (const float*)d_in[2];
    const float* fc_b = (const float*)d_in[3];

    int n_items  = in_sizes[0] / DIM;   // 262144
    int ntiles16 = n_items / 16;        // 16384 16-row units

    cudaFuncSetAttribute(qnn_main, cudaFuncAttributeMaxDynamicSharedMemorySize, SMEM_BYTES);

    qnn_build<<<DIM, 32>>>(wts, fc_w, fc_b);
    qnn_main<<<GRIDB, 256, SMEM_BYTES>>>((const float4*)x, (float4*)d_out, ntiles16);
}